// round 4
// baseline (speedup 1.0000x reference)
#include <cuda_runtime.h>
#include <math.h>

// Problem constants (from reference)
#define NN 50000
#define EE 800000

// ---------------- scratch (static __device__, no runtime alloc) -------------
__device__ float  g_xl[NN * 128];
__device__ float  g_xr[NN * 128];
__device__ float  g_h[NN * 128];        // post-norm1 hidden
__device__ float  g_H1[NN * 512];       // FFN intermediate
__device__ float  g_logits[EE * 4];
__device__ float4 g_plog[EE];           // logits permuted into CSR order
__device__ int    g_psrc[EE];           // src ids permuted into CSR order
__device__ int    g_rowptr[NN + 1];
__device__ int    g_cursor[NN];
__device__ int    g_deg[NN];

// ============================ tiled SGEMM ===================================
// C[M,N] = epilogue(A[M,K] @ B[K,N] + bias)
// EPI 0: +bias            EPI 1: gelu(.+bias)        EPI 2: rmsnorm(res + . + bias)*wnorm (N==128)
template <int EPI>
__launch_bounds__(256, 2)
__global__ void sgemm_kernel(const float* __restrict__ A, const float* __restrict__ B,
                             const float* __restrict__ bias, const float* __restrict__ res,
                             const float* __restrict__ wnorm, float* __restrict__ C,
                             int M, int N, int K) {
    __shared__ float As[16][128];
    __shared__ float Bs[16][128];
    __shared__ float red[128 * 16];
    __shared__ float rowssq[128];

    int tid = threadIdx.x;
    int tx = tid & 15, ty = tid >> 4;
    int rowBase = blockIdx.x * 128;
    int colBase = blockIdx.y * 128;

    float acc[8][8];
#pragma unroll
    for (int i = 0; i < 8; i++)
#pragma unroll
        for (int j = 0; j < 8; j++) acc[i][j] = 0.f;

    int ar = tid >> 1, akk = (tid & 1) * 8;   // A tile load map (row, k-offset)
    int bk = tid >> 4, bc = (tid & 15) * 8;   // B tile load map (k, col-offset)
    bool aval = (rowBase + ar) < M;
    const float* aptr = A + (size_t)(rowBase + ar) * K + akk;
    const float* bptr = B + (size_t)bk * N + colBase + bc;

    for (int k0 = 0; k0 < K; k0 += 16) {
        float4 a0, a1;
        if (aval) {
            a0 = *(const float4*)(aptr + k0);
            a1 = *(const float4*)(aptr + k0 + 4);
        } else {
            a0 = make_float4(0.f, 0.f, 0.f, 0.f); a1 = a0;
        }
        float4 b0 = *(const float4*)(bptr + (size_t)k0 * N);
        float4 b1 = *(const float4*)(bptr + (size_t)k0 * N + 4);

        As[akk + 0][ar] = a0.x; As[akk + 1][ar] = a0.y;
        As[akk + 2][ar] = a0.z; As[akk + 3][ar] = a0.w;
        As[akk + 4][ar] = a1.x; As[akk + 5][ar] = a1.y;
        As[akk + 6][ar] = a1.z; As[akk + 7][ar] = a1.w;
        *(float4*)&Bs[bk][bc] = b0;
        *(float4*)&Bs[bk][bc + 4] = b1;
        __syncthreads();

#pragma unroll
        for (int k = 0; k < 16; k++) {
            float ra[8], rb[8];
            *(float4*)ra       = *(const float4*)&As[k][ty * 8];
            *(float4*)(ra + 4) = *(const float4*)&As[k][ty * 8 + 4];
            *(float4*)rb       = *(const float4*)&Bs[k][tx * 8];
            *(float4*)(rb + 4) = *(const float4*)&Bs[k][tx * 8 + 4];
#pragma unroll
            for (int i = 0; i < 8; i++)
#pragma unroll
                for (int j = 0; j < 8; j++)
                    acc[i][j] = fmaf(ra[i], rb[j], acc[i][j]);
        }
        __syncthreads();
    }

    if (EPI == 0 || EPI == 1) {
#pragma unroll
        for (int i = 0; i < 8; i++) {
            int r = rowBase + ty * 8 + i;
            if (r >= M) continue;
#pragma unroll
            for (int j = 0; j < 8; j++) {
                int c = colBase + tx * 8 + j;
                float v = acc[i][j] + bias[c];
                if (EPI == 1) v = 0.5f * v * (1.f + erff(v * 0.70710678118654752f));
                C[(size_t)r * N + c] = v;
            }
        }
    } else {
        // fused residual + rmsnorm epilogue, tile spans full 128-wide row
#pragma unroll
        for (int i = 0; i < 8; i++) {
            int r = rowBase + ty * 8 + i;
            float p = 0.f;
#pragma unroll
            for (int j = 0; j < 8; j++) {
                int c = tx * 8 + j;
                float v = acc[i][j] + bias[c] + (r < M ? res[(size_t)r * 128 + c] : 0.f);
                acc[i][j] = v;
                p += v * v;
            }
            red[(ty * 8 + i) * 16 + tx] = p;
        }
        __syncthreads();
        if (tid < 128) {
            float s = 0.f;
#pragma unroll
            for (int q = 0; q < 16; q++) s += red[tid * 16 + q];
            rowssq[tid] = s;
        }
        __syncthreads();
#pragma unroll
        for (int i = 0; i < 8; i++) {
            int r = rowBase + ty * 8 + i;
            if (r >= M) continue;
            float scale = rsqrtf(rowssq[ty * 8 + i] * (1.f / 128.f) + 1.1920928955078125e-07f);
#pragma unroll
            for (int j = 0; j < 8; j++) {
                int c = tx * 8 + j;
                C[(size_t)r * 128 + c] = acc[i][j] * scale * wnorm[c];
            }
        }
    }
}

// ============================ CSR build =====================================
__global__ void hist_kernel(const int* __restrict__ ei, int E) {
    int e = blockIdx.x * blockDim.x + threadIdx.x;
    if (e < E) atomicAdd(&g_deg[ei[E + e]], 1);
}

__global__ void scan_kernel(int n) {
    __shared__ int ts[1024];
    int t = threadIdx.x;
    int CH = (n + 1023) / 1024;
    int base = t * CH;
    int s = 0;
    for (int i = 0; i < CH; i++) {
        int idx = base + i;
        if (idx < n) s += g_deg[idx];
    }
    ts[t] = s;
    __syncthreads();
    for (int off = 1; off < 1024; off <<= 1) {
        int v = (t >= off) ? ts[t - off] : 0;
        __syncthreads();
        ts[t] += v;
        __syncthreads();
    }
    int run = t ? ts[t - 1] : 0;
    for (int i = 0; i < CH; i++) {
        int idx = base + i;
        if (idx < n) {
            g_rowptr[idx] = run;
            g_cursor[idx] = run;
            run += g_deg[idx];
        }
    }
    if (t == 1023) g_rowptr[n] = run;
}

// ========================= per-edge logits ==================================
__global__ void edge_logits_kernel(const int* __restrict__ ei, const float* __restrict__ ea,
                                   const float* __restrict__ We, const float* __restrict__ att,
                                   const float* __restrict__ xl, const float* __restrict__ xr,
                                   int E) {
    __shared__ float sWe[2048];
    __shared__ float sAtt[128];
    for (int i = threadIdx.x; i < 2048; i += blockDim.x) sWe[i] = We[i];
    if (threadIdx.x < 128) sAtt[threadIdx.x] = att[threadIdx.x];
    __syncthreads();

    int lane = threadIdx.x & 31;
    int wpb = blockDim.x >> 5;
    int gw = blockIdx.x * wpb + (threadIdx.x >> 5);
    int nw = gridDim.x * wpb;

    for (int e = gw; e < E; e += nw) {
        int src = ei[e];
        int dst = ei[E + e];
        float a = (lane < 16) ? ea[(size_t)e * 16 + lane] : 0.f;
        float av[16];
#pragma unroll
        for (int k = 0; k < 16; k++) av[k] = __shfl_sync(0xffffffffu, a, k);

        float lg[4];
#pragma unroll
        for (int h = 0; h < 4; h++) {
            int c = h * 32 + lane;
            float ev = 0.f;
#pragma unroll
            for (int k = 0; k < 16; k++) ev = fmaf(av[k], sWe[k * 128 + c], ev);
            float m = xl[(size_t)src * 128 + c] + xr[(size_t)dst * 128 + c] + ev;
            float s = (m > 0.f) ? m : 0.2f * m;   // LeakyReLU(0.2)
            lg[h] = s * sAtt[c];
        }
#pragma unroll
        for (int h = 0; h < 4; h++)
#pragma unroll
            for (int off = 16; off; off >>= 1)
                lg[h] += __shfl_xor_sync(0xffffffffu, lg[h], off);
        if (lane == 0)
            *(float4*)(g_logits + (size_t)e * 4) = make_float4(lg[0], lg[1], lg[2], lg[3]);
    }
}

// ============= scatter edges into CSR order (src + logits) ==================
__global__ void scatter_kernel(const int* __restrict__ ei, int E) {
    int e = blockIdx.x * blockDim.x + threadIdx.x;
    if (e >= E) return;
    int dst = ei[E + e];
    int pos = atomicAdd(&g_cursor[dst], 1);
    g_psrc[pos] = ei[e];
    g_plog[pos] = *(const float4*)(g_logits + (size_t)e * 4);
}

// ======== per-node softmax-aggregate + bias + residual + rmsnorm1 ===========
__global__ void gather_norm_kernel(const float* __restrict__ x,
                                   const float* __restrict__ bias_gat,
                                   const float* __restrict__ wn1,
                                   const float* __restrict__ xl, int N) {
    int lane = threadIdx.x & 31;
    int n = blockIdx.x * (blockDim.x >> 5) + (threadIdx.x >> 5);
    if (n >= N) return;
    int beg = g_rowptr[n], end = g_rowptr[n + 1];

    // pass 1: per-head max (streaming, coalesced)
    float mx0 = -INFINITY, mx1 = -INFINITY, mx2 = -INFINITY, mx3 = -INFINITY;
    for (int j = beg + lane; j < end; j += 32) {
        float4 l = g_plog[j];
        mx0 = fmaxf(mx0, l.x); mx1 = fmaxf(mx1, l.y);
        mx2 = fmaxf(mx2, l.z); mx3 = fmaxf(mx3, l.w);
    }
#pragma unroll
    for (int off = 16; off; off >>= 1) {
        mx0 = fmaxf(mx0, __shfl_xor_sync(0xffffffffu, mx0, off));
        mx1 = fmaxf(mx1, __shfl_xor_sync(0xffffffffu, mx1, off));
        mx2 = fmaxf(mx2, __shfl_xor_sync(0xffffffffu, mx2, off));
        mx3 = fmaxf(mx3, __shfl_xor_sync(0xffffffffu, mx3, off));
    }

    // pass 2: whole warp per edge; acc = sum ex*xl[src], den = sum ex
    float acc0 = 0.f, acc1 = 0.f, acc2 = 0.f, acc3 = 0.f;
    float den0 = 0.f, den1 = 0.f, den2 = 0.f, den3 = 0.f;
    for (int j = beg; j < end; j++) {
        int src = g_psrc[j];
        float4 l = g_plog[j];
        float e0 = __expf(l.x - mx0);
        float e1 = __expf(l.y - mx1);
        float e2 = __expf(l.z - mx2);
        float e3 = __expf(l.w - mx3);
        const float* row = xl + (size_t)src * 128;
        acc0 = fmaf(e0, row[lane],      acc0);
        acc1 = fmaf(e1, row[32 + lane], acc1);
        acc2 = fmaf(e2, row[64 + lane], acc2);
        acc3 = fmaf(e3, row[96 + lane], acc3);
        den0 += e0; den1 += e1; den2 += e2; den3 += e3;
    }

    size_t rb = (size_t)n * 128;
    float v0 = acc0 / (den0 + 1e-16f) + bias_gat[lane]      + x[rb + lane];
    float v1 = acc1 / (den1 + 1e-16f) + bias_gat[32 + lane] + x[rb + 32 + lane];
    float v2 = acc2 / (den2 + 1e-16f) + bias_gat[64 + lane] + x[rb + 64 + lane];
    float v3 = acc3 / (den3 + 1e-16f) + bias_gat[96 + lane] + x[rb + 96 + lane];

    float ssq = v0 * v0 + v1 * v1 + v2 * v2 + v3 * v3;
#pragma unroll
    for (int off = 16; off; off >>= 1)
        ssq += __shfl_xor_sync(0xffffffffu, ssq, off);
    float scale = rsqrtf(ssq * (1.f / 128.f) + 1.1920928955078125e-07f);

    g_h[rb + lane]      = v0 * scale * wn1[lane];
    g_h[rb + 32 + lane] = v1 * scale * wn1[32 + lane];
    g_h[rb + 64 + lane] = v2 * scale * wn1[64 + lane];
    g_h[rb + 96 + lane] = v3 * scale * wn1[96 + lane];
}

// ================================ launch ====================================
extern "C" void kernel_launch(void* const* d_in, const int* in_sizes, int n_in,
                              void* d_out, int out_size) {
    const float* x        = (const float*)d_in[0];
    const int*   ei       = (const int*)  d_in[1];
    const float* ea       = (const float*)d_in[2];
    const float* Wl       = (const float*)d_in[3];
    const float* bl       = (const float*)d_in[4];
    const float* Wr       = (const float*)d_in[5];
    const float* br       = (const float*)d_in[6];
    const float* We       = (const float*)d_in[7];
    const float* att      = (const float*)d_in[8];
    const float* bias_gat = (const float*)d_in[9];
    const float* wn1      = (const float*)d_in[10];
    const float* wn2      = (const float*)d_in[11];
    const float* w1       = (const float*)d_in[12];
    const float* b1       = (const float*)d_in[13];
    const float* w2       = (const float*)d_in[14];
    const float* b2       = (const float*)d_in[15];

    int N = in_sizes[0] / 128;
    int E = in_sizes[1] / 2;

    void *p_xl, *p_xr, *p_h, *p_H1, *p_deg;
    cudaGetSymbolAddress(&p_xl, g_xl);
    cudaGetSymbolAddress(&p_xr, g_xr);
    cudaGetSymbolAddress(&p_h, g_h);
    cudaGetSymbolAddress(&p_H1, g_H1);
    cudaGetSymbolAddress(&p_deg, g_deg);

    cudaMemsetAsync(p_deg, 0, (size_t)N * sizeof(int));

    int gx = (N + 127) / 128;

    // node transforms
    sgemm_kernel<0><<<dim3(gx, 1), 256>>>(x, Wl, bl, nullptr, nullptr, (float*)p_xl, N, 128, 128);
    sgemm_kernel<0><<<dim3(gx, 1), 256>>>(x, Wr, br, nullptr, nullptr, (float*)p_xr, N, 128, 128);

    // CSR build (independent of xl/xr; same stream so it just pipelines)
    hist_kernel<<<(E + 255) / 256, 256>>>(ei, E);
    scan_kernel<<<1, 1024>>>(N);

    // per-edge attention logits
    edge_logits_kernel<<<1184, 256>>>(ei, ea, We, att, (const float*)p_xl, (const float*)p_xr, E);

    // permute (src, logits) into CSR order
    scatter_kernel<<<(E + 255) / 256, 256>>>(ei, E);

    // per-node softmax aggregation + bias + residual + rmsnorm1 -> g_h
    gather_norm_kernel<<<(N + 7) / 8, 256>>>(x, bias_gat, wn1, (const float*)p_xl, N);

    // FFN: gelu(h@W1+b1) -> H1 ; rmsnorm(h + H1@W2+b2)*wn2 -> out
    sgemm_kernel<1><<<dim3(gx, 4), 256>>>((const float*)p_h, w1, b1, nullptr, nullptr, (float*)p_H1, N, 512, 128);
    sgemm_kernel<2><<<dim3(gx, 1), 256>>>((const float*)p_H1, w2, b2, (const float*)p_h, wn2, (float*)d_out, N, 128, 512);
}

// round 5
// speedup vs baseline: 1.4676x; 1.4676x over previous
#include <cuda_runtime.h>
#include <math.h>
#include <stdint.h>

#define NN 50000
#define EE 800000

// ---------------- scratch (static __device__, no runtime alloc) -------------
__device__ float  g_xl[NN * 128];
__device__ float  g_xr[NN * 128];       // also reused as FFN gemm2 temp output
__device__ float  g_h[NN * 128];        // post-norm1 hidden
__device__ float  g_H1[NN * 512];       // FFN intermediate
__device__ float  g_logits[EE * 4];
__device__ float4 g_plog[EE];           // logits permuted into CSR order
__device__ int    g_psrc[EE];           // src ids permuted into CSR order
__device__ int    g_rowptr[NN + 1];
__device__ int    g_cursor[NN];
__device__ int    g_deg[NN];

// ============================ tf32 tensor-core GEMM =========================
__device__ __forceinline__ uint32_t f2tf32(float f) {
    uint32_t r;
    asm("cvt.rna.tf32.f32 %0, %1;" : "=r"(r) : "f"(f));
    return r;
}

__device__ __forceinline__ void mma_tf32(float c[4], const uint32_t a[4], const uint32_t b[2]) {
    asm volatile(
        "mma.sync.aligned.m16n8k8.row.col.f32.tf32.tf32.f32 "
        "{%0,%1,%2,%3}, {%4,%5,%6,%7}, {%8,%9}, {%0,%1,%2,%3};"
        : "+f"(c[0]), "+f"(c[1]), "+f"(c[2]), "+f"(c[3])
        : "r"(a[0]), "r"(a[1]), "r"(a[2]), "r"(a[3]), "r"(b[0]), "r"(b[1]));
}

// C[M,N] = epilogue(A[M,K] @ B[K,N] + bias)
// EPI 0: +bias    EPI 1: gelu(. + bias)
// Block tile 128x128, 256 threads (8 warps, each 32 rows x 64 cols).
template <int EPI>
__launch_bounds__(256)
__global__ void tf32gemm_kernel(const float* __restrict__ A, const float* __restrict__ B,
                                const float* __restrict__ bias, float* __restrict__ C,
                                int M, int N, int K) {
    __shared__ uint32_t As[16][136];   // [k][m], pad 136 (mod 32 = 8) -> conflict-free frags
    __shared__ uint32_t Bs[16][136];   // [k][n]

    int tid = threadIdx.x;
    int wid = tid >> 5, lane = tid & 31;
    int g = lane >> 2, tg = lane & 3;
    int wr = (wid & 3) * 32;    // warp row offset within 128
    int wc = (wid >> 2) * 64;   // warp col offset within 128

    int rowBase = blockIdx.x * 128;
    int colBase = blockIdx.y * 128;

    float acc[2][8][4];
#pragma unroll
    for (int mt = 0; mt < 2; mt++)
#pragma unroll
        for (int nt = 0; nt < 8; nt++)
#pragma unroll
            for (int q = 0; q < 4; q++) acc[mt][nt][q] = 0.f;

    // global->smem mapping (same as before, plus tf32 convert)
    int ar = tid >> 1, ak = (tid & 1) * 8;
    int bk = tid >> 4, bc = (tid & 15) * 8;
    bool aval = (rowBase + ar) < M;
    const float* aptr = A + (size_t)(rowBase + ar) * K + ak;
    const float* bptr = B + (size_t)bk * N + colBase + bc;

    for (int k0 = 0; k0 < K; k0 += 16) {
        float4 a0, a1;
        if (aval) {
            a0 = *(const float4*)(aptr + k0);
            a1 = *(const float4*)(aptr + k0 + 4);
        } else {
            a0 = make_float4(0.f, 0.f, 0.f, 0.f); a1 = a0;
        }
        float4 b0 = *(const float4*)(bptr + (size_t)k0 * N);
        float4 b1 = *(const float4*)(bptr + (size_t)k0 * N + 4);

        As[ak + 0][ar] = f2tf32(a0.x); As[ak + 1][ar] = f2tf32(a0.y);
        As[ak + 2][ar] = f2tf32(a0.z); As[ak + 3][ar] = f2tf32(a0.w);
        As[ak + 4][ar] = f2tf32(a1.x); As[ak + 5][ar] = f2tf32(a1.y);
        As[ak + 6][ar] = f2tf32(a1.z); As[ak + 7][ar] = f2tf32(a1.w);
        Bs[bk][bc + 0] = f2tf32(b0.x); Bs[bk][bc + 1] = f2tf32(b0.y);
        Bs[bk][bc + 2] = f2tf32(b0.z); Bs[bk][bc + 3] = f2tf32(b0.w);
        Bs[bk][bc + 4] = f2tf32(b1.x); Bs[bk][bc + 5] = f2tf32(b1.y);
        Bs[bk][bc + 6] = f2tf32(b1.z); Bs[bk][bc + 7] = f2tf32(b1.w);
        __syncthreads();

#pragma unroll
        for (int kk = 0; kk < 16; kk += 8) {
            uint32_t afr[2][4];
#pragma unroll
            for (int mt = 0; mt < 2; mt++) {
                int r = wr + mt * 16;
                afr[mt][0] = As[kk + tg][r + g];
                afr[mt][1] = As[kk + tg][r + g + 8];
                afr[mt][2] = As[kk + tg + 4][r + g];
                afr[mt][3] = As[kk + tg + 4][r + g + 8];
            }
            uint32_t bfr[8][2];
#pragma unroll
            for (int nt = 0; nt < 8; nt++) {
                int cc = wc + nt * 8 + g;
                bfr[nt][0] = Bs[kk + tg][cc];
                bfr[nt][1] = Bs[kk + tg + 4][cc];
            }
#pragma unroll
            for (int mt = 0; mt < 2; mt++)
#pragma unroll
                for (int nt = 0; nt < 8; nt++)
                    mma_tf32(acc[mt][nt], afr[mt], bfr[nt]);
        }
        __syncthreads();
    }

    // epilogue: c0 -> (g, 2tg), c1 -> (g, 2tg+1), c2 -> (g+8, 2tg), c3 -> (g+8, 2tg+1)
#pragma unroll
    for (int mt = 0; mt < 2; mt++) {
        int r0 = rowBase + wr + mt * 16 + g;
        int r1 = r0 + 8;
#pragma unroll
        for (int nt = 0; nt < 8; nt++) {
            int col = colBase + wc + nt * 8 + tg * 2;
            float bi0 = bias[col], bi1 = bias[col + 1];
            float v00 = acc[mt][nt][0] + bi0, v01 = acc[mt][nt][1] + bi1;
            float v10 = acc[mt][nt][2] + bi0, v11 = acc[mt][nt][3] + bi1;
            if (EPI == 1) {
                v00 = 0.5f * v00 * (1.f + erff(v00 * 0.70710678118654752f));
                v01 = 0.5f * v01 * (1.f + erff(v01 * 0.70710678118654752f));
                v10 = 0.5f * v10 * (1.f + erff(v10 * 0.70710678118654752f));
                v11 = 0.5f * v11 * (1.f + erff(v11 * 0.70710678118654752f));
            }
            if (r0 < M) *(float2*)(C + (size_t)r0 * N + col) = make_float2(v00, v01);
            if (r1 < M) *(float2*)(C + (size_t)r1 * N + col) = make_float2(v10, v11);
        }
    }
}

// ================= residual + rmsnorm (warp per row, HID=128) ===============
__global__ void addnorm_kernel(const float* __restrict__ a, const float* __restrict__ res,
                               const float* __restrict__ w, float* __restrict__ out, int N) {
    int lane = threadIdx.x & 31;
    int n = blockIdx.x * (blockDim.x >> 5) + (threadIdx.x >> 5);
    if (n >= N) return;
    size_t base = (size_t)n * 128 + lane * 4;
    float4 va = *(const float4*)(a + base);
    float4 vr = *(const float4*)(res + base);
    float4 v = make_float4(va.x + vr.x, va.y + vr.y, va.z + vr.z, va.w + vr.w);
    float ssq = v.x * v.x + v.y * v.y + v.z * v.z + v.w * v.w;
#pragma unroll
    for (int off = 16; off; off >>= 1)
        ssq += __shfl_xor_sync(0xffffffffu, ssq, off);
    float s = rsqrtf(ssq * (1.f / 128.f) + 1.1920928955078125e-07f);
    float4 vw = *(const float4*)(w + lane * 4);
    *(float4*)(out + base) = make_float4(v.x * s * vw.x, v.y * s * vw.y,
                                         v.z * s * vw.z, v.w * s * vw.w);
}

// ============================ CSR build =====================================
__global__ void hist_kernel(const int* __restrict__ ei, int E) {
    int e = blockIdx.x * blockDim.x + threadIdx.x;
    if (e < E) atomicAdd(&g_deg[ei[E + e]], 1);
}

// coalesced chunked block scan, 1024 threads, one block
__global__ void scan_kernel(int n) {
    __shared__ int wsum[32];
    int t = threadIdx.x, lane = t & 31, w = t >> 5;
    int carry = 0;
    for (int base = 0; base < n; base += 1024) {
        int idx = base + t;
        int v = (idx < n) ? g_deg[idx] : 0;
        int s = v;
#pragma unroll
        for (int o = 1; o < 32; o <<= 1) {
            int u = __shfl_up_sync(0xffffffffu, s, o);
            if (lane >= o) s += u;
        }
        if (lane == 31) wsum[w] = s;
        __syncthreads();
        if (w == 0) {
            int xv = wsum[lane];
#pragma unroll
            for (int o = 1; o < 32; o <<= 1) {
                int u = __shfl_up_sync(0xffffffffu, xv, o);
                if (lane >= o) xv += u;
            }
            wsum[lane] = xv;
        }
        __syncthreads();
        int excl = carry + (w ? wsum[w - 1] : 0) + s - v;
        if (idx < n) { g_rowptr[idx] = excl; g_cursor[idx] = excl; }
        carry += wsum[31];
        __syncthreads();
    }
    if (t == 0) g_rowptr[n] = carry;
}

// ========================= per-edge logits ==================================
__global__ void edge_logits_kernel(const int* __restrict__ ei, const float* __restrict__ ea,
                                   const float* __restrict__ We, const float* __restrict__ att,
                                   const float* __restrict__ xl, const float* __restrict__ xr,
                                   int E) {
    __shared__ float sWe[2048];
    __shared__ float sAtt[128];
    for (int i = threadIdx.x; i < 2048; i += blockDim.x) sWe[i] = We[i];
    if (threadIdx.x < 128) sAtt[threadIdx.x] = att[threadIdx.x];
    __syncthreads();

    int lane = threadIdx.x & 31;
    int wpb = blockDim.x >> 5;
    int gw = blockIdx.x * wpb + (threadIdx.x >> 5);
    int nw = gridDim.x * wpb;

    for (int e = gw; e < E; e += nw) {
        int src = ei[e];
        int dst = ei[E + e];
        float a = (lane < 16) ? ea[(size_t)e * 16 + lane] : 0.f;
        float av[16];
#pragma unroll
        for (int k = 0; k < 16; k++) av[k] = __shfl_sync(0xffffffffu, a, k);

        float lg[4];
#pragma unroll
        for (int h = 0; h < 4; h++) {
            int c = h * 32 + lane;
            float ev = 0.f;
#pragma unroll
            for (int k = 0; k < 16; k++) ev = fmaf(av[k], sWe[k * 128 + c], ev);
            float m = xl[(size_t)src * 128 + c] + xr[(size_t)dst * 128 + c] + ev;
            float s = (m > 0.f) ? m : 0.2f * m;   // LeakyReLU(0.2)
            lg[h] = s * sAtt[c];
        }
#pragma unroll
        for (int h = 0; h < 4; h++)
#pragma unroll
            for (int off = 16; off; off >>= 1)
                lg[h] += __shfl_xor_sync(0xffffffffu, lg[h], off);
        if (lane == 0)
            *(float4*)(g_logits + (size_t)e * 4) = make_float4(lg[0], lg[1], lg[2], lg[3]);
    }
}

// ============= scatter edges into CSR order (src + logits) ==================
__global__ void scatter_kernel(const int* __restrict__ ei, int E) {
    int e = blockIdx.x * blockDim.x + threadIdx.x;
    if (e >= E) return;
    int dst = ei[E + e];
    int pos = atomicAdd(&g_cursor[dst], 1);
    g_psrc[pos] = ei[e];
    g_plog[pos] = *(const float4*)(g_logits + (size_t)e * 4);
}

// ======== per-node softmax-aggregate + bias + residual + rmsnorm1 ===========
__global__ void gather_norm_kernel(const float* __restrict__ x,
                                   const float* __restrict__ bias_gat,
                                   const float* __restrict__ wn1,
                                   const float* __restrict__ xl, int N) {
    int lane = threadIdx.x & 31;
    int n = blockIdx.x * (blockDim.x >> 5) + (threadIdx.x >> 5);
    if (n >= N) return;
    int beg = g_rowptr[n], end = g_rowptr[n + 1];

    // pass 1: per-head max (streaming, coalesced)
    float mx0 = -INFINITY, mx1 = -INFINITY, mx2 = -INFINITY, mx3 = -INFINITY;
    for (int j = beg + lane; j < end; j += 32) {
        float4 l = g_plog[j];
        mx0 = fmaxf(mx0, l.x); mx1 = fmaxf(mx1, l.y);
        mx2 = fmaxf(mx2, l.z); mx3 = fmaxf(mx3, l.w);
    }
#pragma unroll
    for (int off = 16; off; off >>= 1) {
        mx0 = fmaxf(mx0, __shfl_xor_sync(0xffffffffu, mx0, off));
        mx1 = fmaxf(mx1, __shfl_xor_sync(0xffffffffu, mx1, off));
        mx2 = fmaxf(mx2, __shfl_xor_sync(0xffffffffu, mx2, off));
        mx3 = fmaxf(mx3, __shfl_xor_sync(0xffffffffu, mx3, off));
    }

    // pass 2: whole warp per edge; acc = sum ex*xl[src], den = sum ex
    float acc0 = 0.f, acc1 = 0.f, acc2 = 0.f, acc3 = 0.f;
    float den0 = 0.f, den1 = 0.f, den2 = 0.f, den3 = 0.f;
    for (int j = beg; j < end; j++) {
        int src = g_psrc[j];
        float4 l = g_plog[j];
        float e0 = __expf(l.x - mx0);
        float e1 = __expf(l.y - mx1);
        float e2 = __expf(l.z - mx2);
        float e3 = __expf(l.w - mx3);
        const float* row = xl + (size_t)src * 128;
        acc0 = fmaf(e0, row[lane],      acc0);
        acc1 = fmaf(e1, row[32 + lane], acc1);
        acc2 = fmaf(e2, row[64 + lane], acc2);
        acc3 = fmaf(e3, row[96 + lane], acc3);
        den0 += e0; den1 += e1; den2 += e2; den3 += e3;
    }

    size_t rb = (size_t)n * 128;
    float v0 = acc0 / (den0 + 1e-16f) + bias_gat[lane]      + x[rb + lane];
    float v1 = acc1 / (den1 + 1e-16f) + bias_gat[32 + lane] + x[rb + 32 + lane];
    float v2 = acc2 / (den2 + 1e-16f) + bias_gat[64 + lane] + x[rb + 64 + lane];
    float v3 = acc3 / (den3 + 1e-16f) + bias_gat[96 + lane] + x[rb + 96 + lane];

    float ssq = v0 * v0 + v1 * v1 + v2 * v2 + v3 * v3;
#pragma unroll
    for (int off = 16; off; off >>= 1)
        ssq += __shfl_xor_sync(0xffffffffu, ssq, off);
    float scale = rsqrtf(ssq * (1.f / 128.f) + 1.1920928955078125e-07f);

    g_h[rb + lane]      = v0 * scale * wn1[lane];
    g_h[rb + 32 + lane] = v1 * scale * wn1[32 + lane];
    g_h[rb + 64 + lane] = v2 * scale * wn1[64 + lane];
    g_h[rb + 96 + lane] = v3 * scale * wn1[96 + lane];
}

// ================================ launch ====================================
extern "C" void kernel_launch(void* const* d_in, const int* in_sizes, int n_in,
                              void* d_out, int out_size) {
    const float* x        = (const float*)d_in[0];
    const int*   ei       = (const int*)  d_in[1];
    const float* ea       = (const float*)d_in[2];
    const float* Wl       = (const float*)d_in[3];
    const float* bl       = (const float*)d_in[4];
    const float* Wr       = (const float*)d_in[5];
    const float* br       = (const float*)d_in[6];
    const float* We       = (const float*)d_in[7];
    const float* att      = (const float*)d_in[8];
    const float* bias_gat = (const float*)d_in[9];
    const float* wn1      = (const float*)d_in[10];
    const float* wn2      = (const float*)d_in[11];
    const float* w1       = (const float*)d_in[12];
    const float* b1       = (const float*)d_in[13];
    const float* w2       = (const float*)d_in[14];
    const float* b2       = (const float*)d_in[15];

    int N = in_sizes[0] / 128;
    int E = in_sizes[1] / 2;

    void *p_xl, *p_xr, *p_h, *p_H1, *p_deg;
    cudaGetSymbolAddress(&p_xl, g_xl);
    cudaGetSymbolAddress(&p_xr, g_xr);
    cudaGetSymbolAddress(&p_h, g_h);
    cudaGetSymbolAddress(&p_H1, g_H1);
    cudaGetSymbolAddress(&p_deg, g_deg);

    cudaMemsetAsync(p_deg, 0, (size_t)N * sizeof(int));

    int gx = (N + 127) / 128;

    // node transforms (tf32 tensor cores)
    tf32gemm_kernel<0><<<dim3(gx, 1), 256>>>(x, Wl, bl, (float*)p_xl, N, 128, 128);
    tf32gemm_kernel<0><<<dim3(gx, 1), 256>>>(x, Wr, br, (float*)p_xr, N, 128, 128);

    // CSR build
    hist_kernel<<<(E + 255) / 256, 256>>>(ei, E);
    scan_kernel<<<1, 1024>>>(N);

    // per-edge attention logits
    edge_logits_kernel<<<1184, 256>>>(ei, ea, We, att, (const float*)p_xl, (const float*)p_xr, E);

    // permute (src, logits) into CSR order
    scatter_kernel<<<(E + 255) / 256, 256>>>(ei, E);

    // per-node softmax aggregation + bias + residual + rmsnorm1 -> g_h
    gather_norm_kernel<<<(N + 7) / 8, 256>>>(x, bias_gat, wn1, (const float*)p_xl, N);

    // FFN: gelu(h@W1+b1) -> H1
    tf32gemm_kernel<1><<<dim3(gx, 4), 256>>>((const float*)p_h, w1, b1, (float*)p_H1, N, 512, 128);
    // H1@W2+b2 -> tmp (reuse g_xr), then rmsnorm(h + tmp)*wn2 -> out
    tf32gemm_kernel<0><<<dim3(gx, 1), 256>>>((const float*)p_H1, w2, b2, (float*)p_xr, N, 128, 512);
    addnorm_kernel<<<(N + 7) / 8, 256>>>((const float*)p_xr, (const float*)p_h, wn2, (float*)d_out, N);
}

// round 6
// speedup vs baseline: 1.6032x; 1.0924x over previous
#include <cuda_runtime.h>
#include <math.h>
#include <stdint.h>

#define NN 50000
#define EE 800000
#define RMS_EPS 1.1920928955078125e-07f

// ---------------- scratch (static __device__, no runtime alloc) -------------
__device__ float  g_xl[NN * 128];
__device__ float  g_h[NN * 128];        // post-norm1 hidden
__device__ float  g_H1[NN * 512];       // FFN intermediate
__device__ float4 g_plog[EE];           // logits in CSR order
__device__ int    g_psrc[EE];           // src ids in CSR order
__device__ int    g_rowptr[NN + 1];
__device__ int    g_cursor[NN];
__device__ int    g_deg[NN];
__device__ int    g_bsum[64];
__device__ int    g_boff[64];

// ============================ tf32 tensor-core GEMM =========================
__device__ __forceinline__ uint32_t f2tf32(float f) {
    uint32_t r;
    asm("cvt.rna.tf32.f32 %0, %1;" : "=r"(r) : "f"(f));
    return r;
}

__device__ __forceinline__ void mma_tf32(float c[4], const uint32_t a[4], const uint32_t b[2]) {
    asm volatile(
        "mma.sync.aligned.m16n8k8.row.col.f32.tf32.tf32.f32 "
        "{%0,%1,%2,%3}, {%4,%5,%6,%7}, {%8,%9}, {%0,%1,%2,%3};"
        : "+f"(c[0]), "+f"(c[1]), "+f"(c[2]), "+f"(c[3])
        : "r"(a[0]), "r"(a[1]), "r"(a[2]), "r"(a[3]), "r"(b[0]), "r"(b[1]));
}

// C[M,N] = epilogue(A[M,K] @ B[K,N] + bias)
// EPI 0: +bias    EPI 1: gelu(.+bias)    EPI 2: rmsnorm(res + . + bias)*wnorm (N==128)
// Block tile 128x128, 256 threads (8 warps, each 32 rows x 64 cols), double-buffered smem.
template <int EPI>
__launch_bounds__(256)
__global__ void tf32gemm_kernel(const float* __restrict__ A, const float* __restrict__ B,
                                const float* __restrict__ bias, const float* __restrict__ res,
                                const float* __restrict__ wnorm, float* __restrict__ C,
                                int M, int N, int K) {
    __shared__ uint32_t As[2][16][136];   // [buf][k][m], pad 136 -> conflict-free frags
    __shared__ uint32_t Bs[2][16][136];   // [buf][k][n]
    __shared__ float red2[128][2];        // EPI 2 row-ssq partials

    int tid = threadIdx.x;
    int wid = tid >> 5, lane = tid & 31;
    int g = lane >> 2, tg = lane & 3;
    int wr = (wid & 3) * 32;
    int wc = (wid >> 2) * 64;

    int rowBase = blockIdx.x * 128;
    int colBase = blockIdx.y * 128;

    float acc[2][8][4];
#pragma unroll
    for (int mt = 0; mt < 2; mt++)
#pragma unroll
        for (int nt = 0; nt < 8; nt++)
#pragma unroll
            for (int q = 0; q < 4; q++) acc[mt][nt][q] = 0.f;

    int ar = tid >> 1, ak = (tid & 1) * 8;
    int bk = tid >> 4, bc = (tid & 15) * 8;
    bool aval = (rowBase + ar) < M;
    const float* aptr = A + (size_t)(rowBase + ar) * K + ak;
    const float* bptr = B + (size_t)bk * N + colBase + bc;

    float4 a0, a1, b0, b1;
    auto ld = [&](int k0) {
        if (aval) {
            a0 = *(const float4*)(aptr + k0);
            a1 = *(const float4*)(aptr + k0 + 4);
        } else {
            a0 = make_float4(0.f, 0.f, 0.f, 0.f); a1 = a0;
        }
        b0 = *(const float4*)(bptr + (size_t)k0 * N);
        b1 = *(const float4*)(bptr + (size_t)k0 * N + 4);
    };
    auto st = [&](int buf) {
        As[buf][ak + 0][ar] = f2tf32(a0.x); As[buf][ak + 1][ar] = f2tf32(a0.y);
        As[buf][ak + 2][ar] = f2tf32(a0.z); As[buf][ak + 3][ar] = f2tf32(a0.w);
        As[buf][ak + 4][ar] = f2tf32(a1.x); As[buf][ak + 5][ar] = f2tf32(a1.y);
        As[buf][ak + 6][ar] = f2tf32(a1.z); As[buf][ak + 7][ar] = f2tf32(a1.w);
        Bs[buf][bk][bc + 0] = f2tf32(b0.x); Bs[buf][bk][bc + 1] = f2tf32(b0.y);
        Bs[buf][bk][bc + 2] = f2tf32(b0.z); Bs[buf][bk][bc + 3] = f2tf32(b0.w);
        Bs[buf][bk][bc + 4] = f2tf32(b1.x); Bs[buf][bk][bc + 5] = f2tf32(b1.y);
        Bs[buf][bk][bc + 6] = f2tf32(b1.z); Bs[buf][bk][bc + 7] = f2tf32(b1.w);
    };
    auto compute = [&](int buf) {
#pragma unroll
        for (int kk = 0; kk < 16; kk += 8) {
            uint32_t afr[2][4];
#pragma unroll
            for (int mt = 0; mt < 2; mt++) {
                int r = wr + mt * 16;
                afr[mt][0] = As[buf][kk + tg][r + g];
                afr[mt][1] = As[buf][kk + tg][r + g + 8];
                afr[mt][2] = As[buf][kk + tg + 4][r + g];
                afr[mt][3] = As[buf][kk + tg + 4][r + g + 8];
            }
            uint32_t bfr[8][2];
#pragma unroll
            for (int nt = 0; nt < 8; nt++) {
                int cc = wc + nt * 8 + g;
                bfr[nt][0] = Bs[buf][kk + tg][cc];
                bfr[nt][1] = Bs[buf][kk + tg + 4][cc];
            }
#pragma unroll
            for (int mt = 0; mt < 2; mt++)
#pragma unroll
                for (int nt = 0; nt < 8; nt++)
                    mma_tf32(acc[mt][nt], afr[mt], bfr[nt]);
        }
    };

    // pipelined mainloop: load k+1 to regs while computing k
    ld(0); st(0); __syncthreads();
    int buf = 0;
    for (int k0 = 16; k0 < K; k0 += 16) {
        ld(k0);
        compute(buf);
        st(buf ^ 1);
        __syncthreads();
        buf ^= 1;
    }
    compute(buf);

    if (EPI == 0 || EPI == 1) {
#pragma unroll
        for (int mt = 0; mt < 2; mt++) {
            int r0 = rowBase + wr + mt * 16 + g;
            int r1 = r0 + 8;
#pragma unroll
            for (int nt = 0; nt < 8; nt++) {
                int col = colBase + wc + nt * 8 + tg * 2;
                float bi0 = bias[col], bi1 = bias[col + 1];
                float v00 = acc[mt][nt][0] + bi0, v01 = acc[mt][nt][1] + bi1;
                float v10 = acc[mt][nt][2] + bi0, v11 = acc[mt][nt][3] + bi1;
                if (EPI == 1) {
                    v00 = 0.5f * v00 * (1.f + erff(v00 * 0.70710678118654752f));
                    v01 = 0.5f * v01 * (1.f + erff(v01 * 0.70710678118654752f));
                    v10 = 0.5f * v10 * (1.f + erff(v10 * 0.70710678118654752f));
                    v11 = 0.5f * v11 * (1.f + erff(v11 * 0.70710678118654752f));
                }
                if (r0 < M) *(float2*)(C + (size_t)r0 * N + col) = make_float2(v00, v01);
                if (r1 < M) *(float2*)(C + (size_t)r1 * N + col) = make_float2(v10, v11);
            }
        }
    } else {
        // fused residual + rmsnorm epilogue; N==128, colBase==0
        float ssq[2][2] = {{0.f, 0.f}, {0.f, 0.f}};
#pragma unroll
        for (int mt = 0; mt < 2; mt++) {
            int r0 = rowBase + wr + mt * 16 + g;
            int r1 = r0 + 8;
#pragma unroll
            for (int nt = 0; nt < 8; nt++) {
                int col = wc + nt * 8 + tg * 2;
                float bi0 = bias[col], bi1 = bias[col + 1];
                float2 re0 = (r0 < M) ? *(const float2*)(res + (size_t)r0 * 128 + col)
                                      : make_float2(0.f, 0.f);
                float2 re1 = (r1 < M) ? *(const float2*)(res + (size_t)r1 * 128 + col)
                                      : make_float2(0.f, 0.f);
                float v00 = acc[mt][nt][0] + bi0 + re0.x, v01 = acc[mt][nt][1] + bi1 + re0.y;
                float v10 = acc[mt][nt][2] + bi0 + re1.x, v11 = acc[mt][nt][3] + bi1 + re1.y;
                acc[mt][nt][0] = v00; acc[mt][nt][1] = v01;
                acc[mt][nt][2] = v10; acc[mt][nt][3] = v11;
                ssq[mt][0] += v00 * v00 + v01 * v01;
                ssq[mt][1] += v10 * v10 + v11 * v11;
            }
        }
        // reduce over the 4 tg lanes sharing each row
#pragma unroll
        for (int mt = 0; mt < 2; mt++)
#pragma unroll
            for (int o = 1; o < 4; o <<= 1) {
                ssq[mt][0] += __shfl_xor_sync(0xffffffffu, ssq[mt][0], o);
                ssq[mt][1] += __shfl_xor_sync(0xffffffffu, ssq[mt][1], o);
            }
        int half = wid >> 2;   // which 64-col half this warp owns
        if (tg == 0) {
#pragma unroll
            for (int mt = 0; mt < 2; mt++) {
                red2[wr + mt * 16 + g][half]     = ssq[mt][0];
                red2[wr + mt * 16 + g + 8][half] = ssq[mt][1];
            }
        }
        __syncthreads();
#pragma unroll
        for (int mt = 0; mt < 2; mt++) {
            int lr0 = wr + mt * 16 + g, lr1 = lr0 + 8;
            float sc0 = rsqrtf((red2[lr0][0] + red2[lr0][1]) * (1.f / 128.f) + RMS_EPS);
            float sc1 = rsqrtf((red2[lr1][0] + red2[lr1][1]) * (1.f / 128.f) + RMS_EPS);
            int r0 = rowBase + lr0, r1 = rowBase + lr1;
#pragma unroll
            for (int nt = 0; nt < 8; nt++) {
                int col = wc + nt * 8 + tg * 2;
                float w0 = wnorm[col], w1 = wnorm[col + 1];
                if (r0 < M) *(float2*)(C + (size_t)r0 * 128 + col) =
                    make_float2(acc[mt][nt][0] * sc0 * w0, acc[mt][nt][1] * sc0 * w1);
                if (r1 < M) *(float2*)(C + (size_t)r1 * 128 + col) =
                    make_float2(acc[mt][nt][2] * sc1 * w0, acc[mt][nt][3] * sc1 * w1);
            }
        }
    }
}

// ============================ CSR build =====================================
__global__ void hist_kernel(const int* __restrict__ ei, int E) {
    int e = blockIdx.x * blockDim.x + threadIdx.x;
    if (e < E) atomicAdd(&g_deg[ei[E + e]], 1);
}

// pass 1: per-block inclusive scan (1024 elems/block), store incl + block sum
__global__ void scan1_kernel(int n) {
    __shared__ int wsum[32];
    int t = threadIdx.x, lane = t & 31, w = t >> 5;
    int idx = blockIdx.x * 1024 + t;
    int v = (idx < n) ? g_deg[idx] : 0;
    int s = v;
#pragma unroll
    for (int o = 1; o < 32; o <<= 1) {
        int u = __shfl_up_sync(0xffffffffu, s, o);
        if (lane >= o) s += u;
    }
    if (lane == 31) wsum[w] = s;
    __syncthreads();
    if (w == 0) {
        int xv = wsum[lane];
#pragma unroll
        for (int o = 1; o < 32; o <<= 1) {
            int u = __shfl_up_sync(0xffffffffu, xv, o);
            if (lane >= o) xv += u;
        }
        wsum[lane] = xv;
    }
    __syncthreads();
    int incl = s + (w ? wsum[w - 1] : 0);
    if (idx < n) g_rowptr[idx] = incl;          // temp: block-local inclusive
    if (t == 1023) g_bsum[blockIdx.x] = incl;   // block total
}

// pass 2: one warp scans the block sums (exclusive) and writes total
__global__ void scan2_kernel(int nb, int n) {
    int lane = threadIdx.x;
    int carry = 0;
    for (int base = 0; base < nb; base += 32) {
        int v = (base + lane < nb) ? g_bsum[base + lane] : 0;
        int s = v;
#pragma unroll
        for (int o = 1; o < 32; o <<= 1) {
            int u = __shfl_up_sync(0xffffffffu, s, o);
            if (lane >= o) s += u;
        }
        if (base + lane < nb) g_boff[base + lane] = carry + s - v;
        carry += __shfl_sync(0xffffffffu, s, 31);
    }
    if (lane == 0) g_rowptr[n] = carry;
}

// pass 3: convert to global exclusive, init cursor
__global__ void scan3_kernel(int n) {
    int idx = blockIdx.x * 1024 + threadIdx.x;
    if (idx < n) {
        int excl = g_rowptr[idx] - g_deg[idx] + g_boff[blockIdx.x];
        g_rowptr[idx] = excl;
        g_cursor[idx] = excl;
    }
}

// ============== per-edge logits, written directly in CSR order ==============
__global__ void edge_logits_kernel(const int* __restrict__ ei, const float* __restrict__ ea,
                                   const float* __restrict__ We, const float* __restrict__ att,
                                   const float* __restrict__ xl, const float* __restrict__ xr,
                                   int E) {
    __shared__ float sWe[2048];
    __shared__ float sAtt[128];
    for (int i = threadIdx.x; i < 2048; i += blockDim.x) sWe[i] = We[i];
    if (threadIdx.x < 128) sAtt[threadIdx.x] = att[threadIdx.x];
    __syncthreads();

    int lane = threadIdx.x & 31;
    int wpb = blockDim.x >> 5;
    int gw = blockIdx.x * wpb + (threadIdx.x >> 5);
    int nw = gridDim.x * wpb;

    for (int e = gw; e < E; e += nw) {
        int src = ei[e];
        int dst = ei[E + e];
        float a = (lane < 16) ? ea[(size_t)e * 16 + lane] : 0.f;
        float av[16];
#pragma unroll
        for (int k = 0; k < 16; k++) av[k] = __shfl_sync(0xffffffffu, a, k);

        float lg[4];
#pragma unroll
        for (int h = 0; h < 4; h++) {
            int c = h * 32 + lane;
            float ev = 0.f;
#pragma unroll
            for (int k = 0; k < 16; k++) ev = fmaf(av[k], sWe[k * 128 + c], ev);
            float m = xl[(size_t)src * 128 + c] + xr[(size_t)dst * 128 + c] + ev;
            float s = (m > 0.f) ? m : 0.2f * m;   // LeakyReLU(0.2)
            lg[h] = s * sAtt[c];
        }
#pragma unroll
        for (int h = 0; h < 4; h++)
#pragma unroll
            for (int off = 16; off; off >>= 1)
                lg[h] += __shfl_xor_sync(0xffffffffu, lg[h], off);
        if (lane == 0) {
            int pos = atomicAdd(&g_cursor[dst], 1);
            g_psrc[pos] = src;
            g_plog[pos] = make_float4(lg[0], lg[1], lg[2], lg[3]);
        }
    }
}

// ======== per-node softmax-aggregate + bias + residual + rmsnorm1 ===========
__global__ void gather_norm_kernel(const float* __restrict__ x,
                                   const float* __restrict__ bias_gat,
                                   const float* __restrict__ wn1,
                                   const float* __restrict__ xl, int N) {
    int lane = threadIdx.x & 31;
    int n = blockIdx.x * (blockDim.x >> 5) + (threadIdx.x >> 5);
    if (n >= N) return;
    int beg = g_rowptr[n], end = g_rowptr[n + 1];

    // pass 1: per-head max (streaming, coalesced)
    float mx0 = -INFINITY, mx1 = -INFINITY, mx2 = -INFINITY, mx3 = -INFINITY;
    for (int j = beg + lane; j < end; j += 32) {
        float4 l = g_plog[j];
        mx0 = fmaxf(mx0, l.x); mx1 = fmaxf(mx1, l.y);
        mx2 = fmaxf(mx2, l.z); mx3 = fmaxf(mx3, l.w);
    }
#pragma unroll
    for (int off = 16; off; off >>= 1) {
        mx0 = fmaxf(mx0, __shfl_xor_sync(0xffffffffu, mx0, off));
        mx1 = fmaxf(mx1, __shfl_xor_sync(0xffffffffu, mx1, off));
        mx2 = fmaxf(mx2, __shfl_xor_sync(0xffffffffu, mx2, off));
        mx3 = fmaxf(mx3, __shfl_xor_sync(0xffffffffu, mx3, off));
    }

    // pass 2: whole warp per edge; acc = sum ex*xl[src], den = sum ex
    float acc0 = 0.f, acc1 = 0.f, acc2 = 0.f, acc3 = 0.f;
    float den0 = 0.f, den1 = 0.f, den2 = 0.f, den3 = 0.f;
    for (int j = beg; j < end; j++) {
        int src = g_psrc[j];
        float4 l = g_plog[j];
        float e0 = __expf(l.x - mx0);
        float e1 = __expf(l.y - mx1);
        float e2 = __expf(l.z - mx2);
        float e3 = __expf(l.w - mx3);
        const float* row = xl + (size_t)src * 128;
        acc0 = fmaf(e0, row[lane],      acc0);
        acc1 = fmaf(e1, row[32 + lane], acc1);
        acc2 = fmaf(e2, row[64 + lane], acc2);
        acc3 = fmaf(e3, row[96 + lane], acc3);
        den0 += e0; den1 += e1; den2 += e2; den3 += e3;
    }

    size_t rb = (size_t)n * 128;
    float v0 = acc0 / (den0 + 1e-16f) + bias_gat[lane]      + x[rb + lane];
    float v1 = acc1 / (den1 + 1e-16f) + bias_gat[32 + lane] + x[rb + 32 + lane];
    float v2 = acc2 / (den2 + 1e-16f) + bias_gat[64 + lane] + x[rb + 64 + lane];
    float v3 = acc3 / (den3 + 1e-16f) + bias_gat[96 + lane] + x[rb + 96 + lane];

    float ssq = v0 * v0 + v1 * v1 + v2 * v2 + v3 * v3;
#pragma unroll
    for (int off = 16; off; off >>= 1)
        ssq += __shfl_xor_sync(0xffffffffu, ssq, off);
    float scale = rsqrtf(ssq * (1.f / 128.f) + RMS_EPS);

    g_h[rb + lane]      = v0 * scale * wn1[lane];
    g_h[rb + 32 + lane] = v1 * scale * wn1[32 + lane];
    g_h[rb + 64 + lane] = v2 * scale * wn1[64 + lane];
    g_h[rb + 96 + lane] = v3 * scale * wn1[96 + lane];
}

// ================================ launch ====================================
extern "C" void kernel_launch(void* const* d_in, const int* in_sizes, int n_in,
                              void* d_out, int out_size) {
    const float* x        = (const float*)d_in[0];
    const int*   ei       = (const int*)  d_in[1];
    const float* ea       = (const float*)d_in[2];
    const float* Wl       = (const float*)d_in[3];
    const float* bl       = (const float*)d_in[4];
    const float* Wr       = (const float*)d_in[5];
    const float* br       = (const float*)d_in[6];
    const float* We       = (const float*)d_in[7];
    const float* att      = (const float*)d_in[8];
    const float* bias_gat = (const float*)d_in[9];
    const float* wn1      = (const float*)d_in[10];
    const float* wn2      = (const float*)d_in[11];
    const float* w1       = (const float*)d_in[12];
    const float* b1       = (const float*)d_in[13];
    const float* w2       = (const float*)d_in[14];
    const float* b2       = (const float*)d_in[15];

    int N = in_sizes[0] / 128;
    int E = in_sizes[1] / 2;

    void *p_xl, *p_h, *p_H1, *p_deg;
    cudaGetSymbolAddress(&p_xl, g_xl);
    cudaGetSymbolAddress(&p_h, g_h);
    cudaGetSymbolAddress(&p_H1, g_H1);
    cudaGetSymbolAddress(&p_deg, g_deg);

    cudaMemsetAsync(p_deg, 0, (size_t)N * sizeof(int));

    int gx = (N + 127) / 128;
    int nb = (N + 1023) / 1024;

    // node transforms (tf32 tensor cores); xr goes into g_H1 head (dead until FFN)
    float* p_xr = (float*)p_H1;
    tf32gemm_kernel<0><<<dim3(gx, 1), 256>>>(x, Wl, bl, nullptr, nullptr, (float*)p_xl, N, 128, 128);
    tf32gemm_kernel<0><<<dim3(gx, 1), 256>>>(x, Wr, br, nullptr, nullptr, p_xr, N, 128, 128);

    // CSR build (parallel 3-pass scan)
    hist_kernel<<<(E + 255) / 256, 256>>>(ei, E);
    scan1_kernel<<<nb, 1024>>>(N);
    scan2_kernel<<<1, 32>>>(nb, N);
    scan3_kernel<<<nb, 1024>>>(N);

    // per-edge attention logits, written directly into CSR slots
    edge_logits_kernel<<<1184, 256>>>(ei, ea, We, att, (const float*)p_xl, p_xr, E);

    // per-node softmax aggregation + bias + residual + rmsnorm1 -> g_h
    gather_norm_kernel<<<(N + 7) / 8, 256>>>(x, bias_gat, wn1, (const float*)p_xl, N);

    // FFN: gelu(h@W1+b1) -> H1 ; rmsnorm(h + H1@W2+b2)*wn2 -> out (fused epilogue)
    tf32gemm_kernel<1><<<dim3(gx, 4), 256>>>((const float*)p_h, w1, b1, nullptr, nullptr, (float*)p_H1, N, 512, 128);
    tf32gemm_kernel<2><<<dim3(gx, 1), 256>>>((const float*)p_H1, w2, b2, (const float*)p_h, wn2, (float*)d_out, N, 128, 512);
}

// round 7
// speedup vs baseline: 1.6769x; 1.0460x over previous
#include <cuda_runtime.h>
#include <math.h>
#include <stdint.h>

#define NN 50000
#define EE 800000
#define RMS_EPS 1.1920928955078125e-07f

// ---------------- scratch (static __device__, no runtime alloc) -------------
__device__ float  g_xl[NN * 128];
__device__ float  g_h[NN * 128];        // post-norm1 hidden
__device__ float  g_H1[NN * 512];       // FFN intermediate (head reused as xr)
__device__ float4 g_plog[EE];           // logits in CSR order
__device__ int    g_psrc[EE];           // src ids in CSR order
__device__ int    g_rowptr[NN + 1];
__device__ int    g_cursor[NN];
__device__ int    g_deg[NN];
__device__ int    g_bsum[64];
__device__ int    g_boff[64];

// ============================ tf32 tensor-core GEMM =========================
__device__ __forceinline__ void mma_tf32(float c[4], const uint32_t a[4], const uint32_t b[2]) {
    asm volatile(
        "mma.sync.aligned.m16n8k8.row.col.f32.tf32.tf32.f32 "
        "{%0,%1,%2,%3}, {%4,%5,%6,%7}, {%8,%9}, {%0,%1,%2,%3};"
        : "+f"(c[0]), "+f"(c[1]), "+f"(c[2]), "+f"(c[3])
        : "r"(a[0]), "r"(a[1]), "r"(a[2]), "r"(a[3]), "r"(b[0]), "r"(b[1]));
}

__device__ __forceinline__ void cp16(uint32_t smem_addr, const float* gptr, bool valid) {
    asm volatile(
        "{\n\t.reg .pred p;\n\t"
        "setp.ne.b32 p, %2, 0;\n\t"
        "@p cp.async.cg.shared.global [%0], [%1], 16;\n\t"
        "@!p cp.async.cg.shared.global [%0], [%1], 16, 0;\n\t}"
        :: "r"(smem_addr), "l"(gptr), "r"((int)valid));
}

#define A_ST 20            // A smem row stride (floats), bank-conflict-free
#define B_ST 136           // B smem row stride
#define A_SZ (128 * A_ST)
#define B_SZ (16 * B_ST)

// C[M,N] = epilogue(A[M,K] @ B[K,N] + bias)
// EPI 0: +bias   EPI 1: gelu(.+bias)   EPI 2: rmsnorm(res + . + bias)*wnorm (N==128)
// DUAL: blockIdx.y selects (B,bias,C) vs (B2,bias2,C2), N==128.
// Block tile 128x128, 256 threads (8 warps x 32rows x 64cols), 2-stage cp.async.
template <int EPI, bool DUAL>
__launch_bounds__(256)
__global__ void tf32gemm_kernel(const float* __restrict__ A, const float* __restrict__ B,
                                const float* __restrict__ bias, const float* __restrict__ res,
                                const float* __restrict__ wnorm, float* __restrict__ C,
                                int M, int N, int K,
                                const float* __restrict__ B2, const float* __restrict__ bias2,
                                float* __restrict__ C2) {
    __shared__ uint32_t As[2][A_SZ];   // [m][k] raw fp32 bits
    __shared__ uint32_t Bs[2][B_SZ];   // [k][n] raw fp32 bits
    __shared__ float red2[128][2];     // EPI 2 row-ssq partials

    if (DUAL && blockIdx.y == 1) { B = B2; bias = bias2; C = C2; }
    int colBase = DUAL ? 0 : blockIdx.y * 128;
    int rowBase = blockIdx.x * 128;

    int tid = threadIdx.x;
    int wid = tid >> 5, lane = tid & 31;
    int g = lane >> 2, tg = lane & 3;
    int wr = (wid & 3) * 32;
    int wc = (wid >> 2) * 64;

    float acc[2][8][4];
#pragma unroll
    for (int mt = 0; mt < 2; mt++)
#pragma unroll
        for (int nt = 0; nt < 8; nt++)
#pragma unroll
            for (int q = 0; q < 4; q++) acc[mt][nt][q] = 0.f;

    int ar = tid >> 1, ak = (tid & 1) * 8;
    int bk = tid >> 4, bc = (tid & 15) * 8;
    bool aval = (rowBase + ar) < M;
    const float* aptr = A + (size_t)(rowBase + ar) * K + ak;
    const float* bptr = B + (size_t)bk * N + colBase + bc;

    uint32_t aBase = (uint32_t)__cvta_generic_to_shared(&As[0][0]) + (ar * A_ST + ak) * 4;
    uint32_t bBase = (uint32_t)__cvta_generic_to_shared(&Bs[0][0]) + (bk * B_ST + bc) * 4;

    auto issue = [&](int chunk, int buf) {
        int k0 = chunk * 16;
        uint32_t da = aBase + buf * (A_SZ * 4);
        cp16(da,      aptr + k0,     aval);
        cp16(da + 16, aptr + k0 + 4, aval);
        uint32_t db = bBase + buf * (B_SZ * 4);
        cp16(db,      bptr + (size_t)k0 * N,     true);
        cp16(db + 16, bptr + (size_t)k0 * N + 4, true);
        asm volatile("cp.async.commit_group;");
    };

    auto compute = [&](int buf) {
#pragma unroll
        for (int kk = 0; kk < 16; kk += 8) {
            uint32_t afr[2][4];
#pragma unroll
            for (int mt = 0; mt < 2; mt++) {
                int r = wr + mt * 16 + g;
                afr[mt][0] = As[buf][r * A_ST + kk + tg] + 0x1000u;
                afr[mt][1] = As[buf][(r + 8) * A_ST + kk + tg] + 0x1000u;
                afr[mt][2] = As[buf][r * A_ST + kk + tg + 4] + 0x1000u;
                afr[mt][3] = As[buf][(r + 8) * A_ST + kk + tg + 4] + 0x1000u;
            }
            uint32_t bfr[8][2];
#pragma unroll
            for (int nt = 0; nt < 8; nt++) {
                int cc = wc + nt * 8 + g;
                bfr[nt][0] = Bs[buf][(kk + tg) * B_ST + cc] + 0x1000u;
                bfr[nt][1] = Bs[buf][(kk + tg + 4) * B_ST + cc] + 0x1000u;
            }
#pragma unroll
            for (int mt = 0; mt < 2; mt++)
#pragma unroll
                for (int nt = 0; nt < 8; nt++)
                    mma_tf32(acc[mt][nt], afr[mt], bfr[nt]);
        }
    };

    int nch = K >> 4;
    issue(0, 0);
    for (int i = 0; i < nch; ++i) {
        if (i + 1 < nch) {
            issue(i + 1, (i + 1) & 1);
            asm volatile("cp.async.wait_group 1;");
        } else {
            asm volatile("cp.async.wait_group 0;");
        }
        __syncthreads();
        compute(i & 1);
        __syncthreads();
    }

    if (EPI == 0 || EPI == 1) {
#pragma unroll
        for (int mt = 0; mt < 2; mt++) {
            int r0 = rowBase + wr + mt * 16 + g;
            int r1 = r0 + 8;
#pragma unroll
            for (int nt = 0; nt < 8; nt++) {
                int col = colBase + wc + nt * 8 + tg * 2;
                float bi0 = bias[col], bi1 = bias[col + 1];
                float v00 = acc[mt][nt][0] + bi0, v01 = acc[mt][nt][1] + bi1;
                float v10 = acc[mt][nt][2] + bi0, v11 = acc[mt][nt][3] + bi1;
                if (EPI == 1) {
                    v00 = 0.5f * v00 * (1.f + erff(v00 * 0.70710678118654752f));
                    v01 = 0.5f * v01 * (1.f + erff(v01 * 0.70710678118654752f));
                    v10 = 0.5f * v10 * (1.f + erff(v10 * 0.70710678118654752f));
                    v11 = 0.5f * v11 * (1.f + erff(v11 * 0.70710678118654752f));
                }
                if (r0 < M) *(float2*)(C + (size_t)r0 * N + col) = make_float2(v00, v01);
                if (r1 < M) *(float2*)(C + (size_t)r1 * N + col) = make_float2(v10, v11);
            }
        }
    } else {
        // fused residual + rmsnorm epilogue; N==128, colBase==0
        float ssq[2][2] = {{0.f, 0.f}, {0.f, 0.f}};
#pragma unroll
        for (int mt = 0; mt < 2; mt++) {
            int r0 = rowBase + wr + mt * 16 + g;
            int r1 = r0 + 8;
#pragma unroll
            for (int nt = 0; nt < 8; nt++) {
                int col = wc + nt * 8 + tg * 2;
                float bi0 = bias[col], bi1 = bias[col + 1];
                float2 re0 = (r0 < M) ? *(const float2*)(res + (size_t)r0 * 128 + col)
                                      : make_float2(0.f, 0.f);
                float2 re1 = (r1 < M) ? *(const float2*)(res + (size_t)r1 * 128 + col)
                                      : make_float2(0.f, 0.f);
                float v00 = acc[mt][nt][0] + bi0 + re0.x, v01 = acc[mt][nt][1] + bi1 + re0.y;
                float v10 = acc[mt][nt][2] + bi0 + re1.x, v11 = acc[mt][nt][3] + bi1 + re1.y;
                acc[mt][nt][0] = v00; acc[mt][nt][1] = v01;
                acc[mt][nt][2] = v10; acc[mt][nt][3] = v11;
                ssq[mt][0] += v00 * v00 + v01 * v01;
                ssq[mt][1] += v10 * v10 + v11 * v11;
            }
        }
#pragma unroll
        for (int mt = 0; mt < 2; mt++)
#pragma unroll
            for (int o = 1; o < 4; o <<= 1) {
                ssq[mt][0] += __shfl_xor_sync(0xffffffffu, ssq[mt][0], o);
                ssq[mt][1] += __shfl_xor_sync(0xffffffffu, ssq[mt][1], o);
            }
        int half = wid >> 2;
        if (tg == 0) {
#pragma unroll
            for (int mt = 0; mt < 2; mt++) {
                red2[wr + mt * 16 + g][half]     = ssq[mt][0];
                red2[wr + mt * 16 + g + 8][half] = ssq[mt][1];
            }
        }
        __syncthreads();
#pragma unroll
        for (int mt = 0; mt < 2; mt++) {
            int lr0 = wr + mt * 16 + g, lr1 = lr0 + 8;
            float sc0 = rsqrtf((red2[lr0][0] + red2[lr0][1]) * (1.f / 128.f) + RMS_EPS);
            float sc1 = rsqrtf((red2[lr1][0] + red2[lr1][1]) * (1.f / 128.f) + RMS_EPS);
            int r0 = rowBase + lr0, r1 = rowBase + lr1;
#pragma unroll
            for (int nt = 0; nt < 8; nt++) {
                int col = wc + nt * 8 + tg * 2;
                float w0 = wnorm[col], w1 = wnorm[col + 1];
                if (r0 < M) *(float2*)(C + (size_t)r0 * 128 + col) =
                    make_float2(acc[mt][nt][0] * sc0 * w0, acc[mt][nt][1] * sc0 * w1);
                if (r1 < M) *(float2*)(C + (size_t)r1 * 128 + col) =
                    make_float2(acc[mt][nt][2] * sc1 * w0, acc[mt][nt][3] * sc1 * w1);
            }
        }
    }
}

// ============================ CSR build =====================================
__global__ void hist_kernel(const int* __restrict__ ei, int E) {
    int e = blockIdx.x * blockDim.x + threadIdx.x;
    if (e < E) atomicAdd(&g_deg[ei[E + e]], 1);
}

__global__ void scan1_kernel(int n) {
    __shared__ int wsum[32];
    int t = threadIdx.x, lane = t & 31, w = t >> 5;
    int idx = blockIdx.x * 1024 + t;
    int v = (idx < n) ? g_deg[idx] : 0;
    int s = v;
#pragma unroll
    for (int o = 1; o < 32; o <<= 1) {
        int u = __shfl_up_sync(0xffffffffu, s, o);
        if (lane >= o) s += u;
    }
    if (lane == 31) wsum[w] = s;
    __syncthreads();
    if (w == 0) {
        int xv = wsum[lane];
#pragma unroll
        for (int o = 1; o < 32; o <<= 1) {
            int u = __shfl_up_sync(0xffffffffu, xv, o);
            if (lane >= o) xv += u;
        }
        wsum[lane] = xv;
    }
    __syncthreads();
    int incl = s + (w ? wsum[w - 1] : 0);
    if (idx < n) g_rowptr[idx] = incl;
    if (t == 1023) g_bsum[blockIdx.x] = incl;
}

__global__ void scan2_kernel(int nb, int n) {
    int lane = threadIdx.x;
    int carry = 0;
    for (int base = 0; base < nb; base += 32) {
        int v = (base + lane < nb) ? g_bsum[base + lane] : 0;
        int s = v;
#pragma unroll
        for (int o = 1; o < 32; o <<= 1) {
            int u = __shfl_up_sync(0xffffffffu, s, o);
            if (lane >= o) s += u;
        }
        if (base + lane < nb) g_boff[base + lane] = carry + s - v;
        carry += __shfl_sync(0xffffffffu, s, 31);
    }
    if (lane == 0) g_rowptr[n] = carry;
}

__global__ void scan3_kernel(int n) {
    int idx = blockIdx.x * 1024 + threadIdx.x;
    if (idx < n) {
        int excl = g_rowptr[idx] - g_deg[idx] + g_boff[blockIdx.x];
        g_rowptr[idx] = excl;
        g_cursor[idx] = excl;
    }
}

// ============== per-edge logits, written directly in CSR order ==============
__global__ void edge_logits_kernel(const int* __restrict__ ei, const float* __restrict__ ea,
                                   const float* __restrict__ We, const float* __restrict__ att,
                                   const float* __restrict__ xl, const float* __restrict__ xr,
                                   int E) {
    __shared__ float sWe[2048];
    __shared__ float sAtt[128];
    for (int i = threadIdx.x; i < 2048; i += blockDim.x) sWe[i] = We[i];
    if (threadIdx.x < 128) sAtt[threadIdx.x] = att[threadIdx.x];
    __syncthreads();

    int lane = threadIdx.x & 31;
    int wpb = blockDim.x >> 5;
    int gw = blockIdx.x * wpb + (threadIdx.x >> 5);
    int nw = gridDim.x * wpb;

    for (int e = gw; e < E; e += nw) {
        int src = ei[e];
        int dst = ei[E + e];
        float a = (lane < 16) ? ea[(size_t)e * 16 + lane] : 0.f;
        float av[16];
#pragma unroll
        for (int k = 0; k < 16; k++) av[k] = __shfl_sync(0xffffffffu, a, k);

        float lg[4];
#pragma unroll
        for (int h = 0; h < 4; h++) {
            int c = h * 32 + lane;
            float ev = 0.f;
#pragma unroll
            for (int k = 0; k < 16; k++) ev = fmaf(av[k], sWe[k * 128 + c], ev);
            float m = xl[(size_t)src * 128 + c] + xr[(size_t)dst * 128 + c] + ev;
            float s = (m > 0.f) ? m : 0.2f * m;   // LeakyReLU(0.2)
            lg[h] = s * sAtt[c];
        }
#pragma unroll
        for (int h = 0; h < 4; h++)
#pragma unroll
            for (int off = 16; off; off >>= 1)
                lg[h] += __shfl_xor_sync(0xffffffffu, lg[h], off);
        if (lane == 0) {
            int pos = atomicAdd(&g_cursor[dst], 1);
            g_psrc[pos] = src;
            g_plog[pos] = make_float4(lg[0], lg[1], lg[2], lg[3]);
        }
    }
}

// ======== per-node softmax-aggregate + bias + residual + rmsnorm1 ===========
__global__ void gather_norm_kernel(const float* __restrict__ x,
                                   const float* __restrict__ bias_gat,
                                   const float* __restrict__ wn1,
                                   const float* __restrict__ xl, int N) {
    int lane = threadIdx.x & 31;
    int n = blockIdx.x * (blockDim.x >> 5) + (threadIdx.x >> 5);
    if (n >= N) return;
    int beg = g_rowptr[n], end = g_rowptr[n + 1];

    float mx0 = -INFINITY, mx1 = -INFINITY, mx2 = -INFINITY, mx3 = -INFINITY;
    for (int j = beg + lane; j < end; j += 32) {
        float4 l = g_plog[j];
        mx0 = fmaxf(mx0, l.x); mx1 = fmaxf(mx1, l.y);
        mx2 = fmaxf(mx2, l.z); mx3 = fmaxf(mx3, l.w);
    }
#pragma unroll
    for (int off = 16; off; off >>= 1) {
        mx0 = fmaxf(mx0, __shfl_xor_sync(0xffffffffu, mx0, off));
        mx1 = fmaxf(mx1, __shfl_xor_sync(0xffffffffu, mx1, off));
        mx2 = fmaxf(mx2, __shfl_xor_sync(0xffffffffu, mx2, off));
        mx3 = fmaxf(mx3, __shfl_xor_sync(0xffffffffu, mx3, off));
    }

    float acc0 = 0.f, acc1 = 0.f, acc2 = 0.f, acc3 = 0.f;
    float den0 = 0.f, den1 = 0.f, den2 = 0.f, den3 = 0.f;
    for (int j = beg; j < end; j++) {
        int src = g_psrc[j];
        float4 l = g_plog[j];
        float e0 = __expf(l.x - mx0);
        float e1 = __expf(l.y - mx1);
        float e2 = __expf(l.z - mx2);
        float e3 = __expf(l.w - mx3);
        const float* row = xl + (size_t)src * 128;
        acc0 = fmaf(e0, row[lane],      acc0);
        acc1 = fmaf(e1, row[32 + lane], acc1);
        acc2 = fmaf(e2, row[64 + lane], acc2);
        acc3 = fmaf(e3, row[96 + lane], acc3);
        den0 += e0; den1 += e1; den2 += e2; den3 += e3;
    }

    size_t rb = (size_t)n * 128;
    float v0 = acc0 / (den0 + 1e-16f) + bias_gat[lane]      + x[rb + lane];
    float v1 = acc1 / (den1 + 1e-16f) + bias_gat[32 + lane] + x[rb + 32 + lane];
    float v2 = acc2 / (den2 + 1e-16f) + bias_gat[64 + lane] + x[rb + 64 + lane];
    float v3 = acc3 / (den3 + 1e-16f) + bias_gat[96 + lane] + x[rb + 96 + lane];

    float ssq = v0 * v0 + v1 * v1 + v2 * v2 + v3 * v3;
#pragma unroll
    for (int off = 16; off; off >>= 1)
        ssq += __shfl_xor_sync(0xffffffffu, ssq, off);
    float scale = rsqrtf(ssq * (1.f / 128.f) + RMS_EPS);

    g_h[rb + lane]      = v0 * scale * wn1[lane];
    g_h[rb + 32 + lane] = v1 * scale * wn1[32 + lane];
    g_h[rb + 64 + lane] = v2 * scale * wn1[64 + lane];
    g_h[rb + 96 + lane] = v3 * scale * wn1[96 + lane];
}

// ================================ launch ====================================
extern "C" void kernel_launch(void* const* d_in, const int* in_sizes, int n_in,
                              void* d_out, int out_size) {
    const float* x        = (const float*)d_in[0];
    const int*   ei       = (const int*)  d_in[1];
    const float* ea       = (const float*)d_in[2];
    const float* Wl       = (const float*)d_in[3];
    const float* bl       = (const float*)d_in[4];
    const float* Wr       = (const float*)d_in[5];
    const float* br       = (const float*)d_in[6];
    const float* We       = (const float*)d_in[7];
    const float* att      = (const float*)d_in[8];
    const float* bias_gat = (const float*)d_in[9];
    const float* wn1      = (const float*)d_in[10];
    const float* wn2      = (const float*)d_in[11];
    const float* w1       = (const float*)d_in[12];
    const float* b1       = (const float*)d_in[13];
    const float* w2       = (const float*)d_in[14];
    const float* b2       = (const float*)d_in[15];

    int N = in_sizes[0] / 128;
    int E = in_sizes[1] / 2;

    void *p_xl, *p_h, *p_H1, *p_deg;
    cudaGetSymbolAddress(&p_xl, g_xl);
    cudaGetSymbolAddress(&p_h, g_h);
    cudaGetSymbolAddress(&p_H1, g_H1);
    cudaGetSymbolAddress(&p_deg, g_deg);

    cudaMemsetAsync(p_deg, 0, (size_t)N * sizeof(int));

    int gx = (N + 127) / 128;
    int nb = (N + 1023) / 1024;
    float* p_xr = (float*)p_H1;   // dead until FFN1 overwrites it

    // xl = x@Wl+bl, xr = x@Wr+br in one dual launch
    tf32gemm_kernel<0, true><<<dim3(gx, 2), 256>>>(x, Wl, bl, nullptr, nullptr, (float*)p_xl,
                                                   N, 128, 128, Wr, br, p_xr);

    // CSR build (parallel 3-pass scan)
    hist_kernel<<<(E + 255) / 256, 256>>>(ei, E);
    scan1_kernel<<<nb, 1024>>>(N);
    scan2_kernel<<<1, 32>>>(nb, N);
    scan3_kernel<<<nb, 1024>>>(N);

    // per-edge attention logits, written directly into CSR slots
    edge_logits_kernel<<<1216, 256>>>(ei, ea, We, att, (const float*)p_xl, p_xr, E);

    // per-node softmax aggregation + bias + residual + rmsnorm1 -> g_h
    gather_norm_kernel<<<(N + 7) / 8, 256>>>(x, bias_gat, wn1, (const float*)p_xl, N);

    // FFN: gelu(h@W1+b1) -> H1 ; rmsnorm(h + H1@W2+b2)*wn2 -> out (fused epilogue)
    tf32gemm_kernel<1, false><<<dim3(gx, 4), 256>>>((const float*)p_h, w1, b1, nullptr, nullptr,
                                                    (float*)p_H1, N, 512, 128,
                                                    nullptr, nullptr, nullptr);
    tf32gemm_kernel<2, false><<<dim3(gx, 1), 256>>>((const float*)p_H1, w2, b2, (const float*)p_h,
                                                    wn2, (float*)d_out, N, 128, 512,
                                                    nullptr, nullptr, nullptr);
}